// round 5
// baseline (speedup 1.0000x reference)
#include <cuda_runtime.h>
#include <cstddef>

#define Bx 16
#define Lx 4096
#define Dx 1024
#define NSPLIT 32
#define ROWS_PER_SPLIT (Lx / NSPLIT)   // 128
#define SBLK 8                         // rows per score block (1 warp/row)
#define NSBLK (Lx / SBLK)              // 512 score blocks per batch

// ---- scratch (__device__ globals; no allocation allowed) ----
__device__ float g_df[Bx * Dx];                // dec_feature
__device__ float g_score[Bx * Lx];             // pre-softmax scores
__device__ float g_partial[Bx * NSPLIT * Dx];  // context partials
__device__ int   g_ctr_s[Bx];                  // score-block arrival counters
__device__ int   g_ctr_c[Bx];                  // context-block arrival counters

// d_out layout (float32): attn, context, new_coverage
#define ATTN_OFF 0
#define CTX_OFF  (Bx * Lx)
#define COV_OFF  (Bx * Lx + Bx * Dx)

__device__ __forceinline__ float tanh_approx(float x) {
    float y;
    asm("tanh.approx.f32 %0, %1;" : "=f"(y) : "f"(x));
    return y;
}

// ============================================================
// Kernel 1: dec_feature[b,d] = sum_k dec_hidden[b,k]*W_feat[d,k] + b_feat[d]
// 16-value x 32-lane reduction via MERGING butterfly: 16 shuffles, not 80.
// ============================================================
__global__ void k_decfeat(const float* __restrict__ dh,
                          const float* __restrict__ W,
                          const float* __restrict__ bias) {
    int d = blockIdx.x;
    int t = threadIdx.x;               // 0..255
    int warp = t >> 5, lane = t & 31;
    float4 w4 = ((const float4*)(W + (size_t)d * Dx))[t];

    float acc[Bx];
#pragma unroll
    for (int b = 0; b < Bx; b++) {
        float4 h4 = ((const float4*)(dh + (size_t)b * Dx))[t];
        acc[b] = w4.x * h4.x + w4.y * h4.y + w4.z * h4.z + w4.w * h4.w;
    }

    // ---- merging butterfly: after each level, half the values remain ----
    bool hi = (lane & 16) != 0;        // level 1 (xor 16): keep 8 values
#pragma unroll
    for (int i = 0; i < 8; i++) {
        float send = hi ? acc[i] : acc[i + 8];
        float r = __shfl_xor_sync(0xffffffffu, send, 16);
        acc[i] = (hi ? acc[i + 8] : acc[i]) + r;   // b = i + 8*hi
    }
    bool h2 = (lane & 8) != 0;         // level 2 (xor 8): keep 4
#pragma unroll
    for (int i = 0; i < 4; i++) {
        float send = h2 ? acc[i] : acc[i + 4];
        float r = __shfl_xor_sync(0xffffffffu, send, 8);
        acc[i] = (h2 ? acc[i + 4] : acc[i]) + r;   // b = i + 4*h2 + 8*hi
    }
    bool h3 = (lane & 4) != 0;         // level 3 (xor 4): keep 2
#pragma unroll
    for (int i = 0; i < 2; i++) {
        float send = h3 ? acc[i] : acc[i + 2];
        float r = __shfl_xor_sync(0xffffffffu, send, 4);
        acc[i] = (h3 ? acc[i + 2] : acc[i]) + r;   // b = i + 2*h3 + ...
    }
    bool h4 = (lane & 2) != 0;         // level 4 (xor 2): keep 1
    {
        float send = h4 ? acc[0] : acc[1];
        float r = __shfl_xor_sync(0xffffffffu, send, 2);
        acc[0] = (h4 ? acc[1] : acc[0]) + r;
    }
    acc[0] += __shfl_xor_sync(0xffffffffu, acc[0], 1);   // level 5 (xor 1)
    // lane now holds full sum for b = (lane >> 1) & 15 (dup in lane^1)

    __shared__ float s[8][Bx];
    if ((lane & 1) == 0) s[warp][(lane >> 1) & 15] = acc[0];
    __syncthreads();
    if (t < Bx) {
        float v = 0.f;
#pragma unroll
        for (int w = 0; w < 8; w++) v += s[w][t];
        g_df[t * Dx + d] = v + bias[d];
    }
}

// ============================================================
// Kernel 2: score (warp-per-row, smem weights, 8-deep load batch)
// + fused masked softmax in the last-arriving block per b.
// ============================================================
__global__ void k_score(const float* __restrict__ ef,
                        const float* __restrict__ cov,
                        const float* __restrict__ wscore,
                        const float* __restrict__ wcov,
                        const float* __restrict__ mask,
                        float* __restrict__ out) {
    int b  = blockIdx.y;
    int l0 = blockIdx.x * SBLK;
    int t = threadIdx.x, w = t >> 5, lane = t & 31;

    __shared__ float4 s_df[Dx / 4], s_ws[Dx / 4], s_wc[Dx / 4];
    __shared__ float  s_red[8];
    __shared__ int    s_last;
    s_df[t] = ((const float4*)(g_df + (size_t)b * Dx))[t];
    s_ws[t] = ((const float4*)wscore)[t];
    s_wc[t] = ((const float4*)wcov)[t];
    __syncthreads();

    int l = l0 + w;
    float c = cov[b * Lx + l];
    const float4* row = (const float4*)(ef + ((size_t)b * Lx + l) * Dx);

    float sum = 0.f;
#pragma unroll
    for (int j = 0; j < 8; j++) {
        int idx = lane + j * 32;
        float4 e  = row[idx];
        float4 dv = s_df[idx];
        float4 wc = s_wc[idx];
        float4 ws = s_ws[idx];
        sum += tanh_approx(fmaf(c, wc.x, e.x + dv.x)) * ws.x
             + tanh_approx(fmaf(c, wc.y, e.y + dv.y)) * ws.y
             + tanh_approx(fmaf(c, wc.z, e.z + dv.z)) * ws.z
             + tanh_approx(fmaf(c, wc.w, e.w + dv.w)) * ws.w;
    }
#pragma unroll
    for (int off = 16; off; off >>= 1)
        sum += __shfl_down_sync(0xffffffffu, sum, off);
    if (lane == 0) g_score[b * Lx + l] = sum;

    // ---- arrival: stores -> bar (cta) -> fence(gpu) -> atomic ----
    __syncthreads();
    if (t == 0) {
        __threadfence();
        int old = atomicAdd(&g_ctr_s[b], 1);
        s_last = (old == NSBLK - 1);
        if (s_last) g_ctr_s[b] = 0;   // reset for next graph replay
    }
    __syncthreads();
    if (!s_last) return;
    __threadfence();

    // ---- last block per b: masked softmax over the full row ----
    const float4* sc = (const float4*)(g_score + (size_t)b * Lx);
    float4 v[4];
#pragma unroll
    for (int k = 0; k < 4; k++) v[k] = sc[t + k * 256];

    float mx = -1e30f;
#pragma unroll
    for (int k = 0; k < 4; k++)
        mx = fmaxf(mx, fmaxf(fmaxf(v[k].x, v[k].y), fmaxf(v[k].z, v[k].w)));
#pragma unroll
    for (int off = 16; off; off >>= 1)
        mx = fmaxf(mx, __shfl_xor_sync(0xffffffffu, mx, off));
    if (lane == 0) s_red[w] = mx;
    __syncthreads();
#pragma unroll
    for (int k = 0; k < 8; k++) mx = fmaxf(mx, s_red[k]);
    __syncthreads();

    // softmax -> *mask -> /sum collapses to em / sum(em)
    const float4* mkp = (const float4*)(mask + (size_t)b * Lx);
    float4 em[4];
    float lsum = 0.f;
#pragma unroll
    for (int k = 0; k < 4; k++) {
        float4 m4 = mkp[t + k * 256];
        em[k].x = expf(v[k].x - mx) * m4.x;
        em[k].y = expf(v[k].y - mx) * m4.y;
        em[k].z = expf(v[k].z - mx) * m4.z;
        em[k].w = expf(v[k].w - mx) * m4.w;
        lsum += em[k].x + em[k].y + em[k].z + em[k].w;
    }
#pragma unroll
    for (int off = 16; off; off >>= 1)
        lsum += __shfl_xor_sync(0xffffffffu, lsum, off);
    if (lane == 0) s_red[w] = lsum;
    __syncthreads();
    float tot = 0.f;
#pragma unroll
    for (int k = 0; k < 8; k++) tot += s_red[k];
    float inv = 1.f / tot;

    const float4* cvp = (const float4*)(cov + (size_t)b * Lx);
    float4* attnp = (float4*)(out + ATTN_OFF + (size_t)b * Lx);
    float4* covp  = (float4*)(out + COV_OFF  + (size_t)b * Lx);
#pragma unroll
    for (int k = 0; k < 4; k++) {
        float4 c4 = cvp[t + k * 256];
        float4 a4;
        a4.x = em[k].x * inv; a4.y = em[k].y * inv;
        a4.z = em[k].z * inv; a4.w = em[k].w * inv;
        attnp[t + k * 256] = a4;
        float4 n4;
        n4.x = a4.x + c4.x; n4.y = a4.y + c4.y;
        n4.z = a4.z + c4.z; n4.w = a4.w + c4.w;
        covp[t + k * 256] = n4;
    }
}

// ============================================================
// Kernel 3: context partials + fused deterministic reduce
// ============================================================
__global__ void __launch_bounds__(256)
k_context(const float* __restrict__ eo,
          const float* __restrict__ attn,
          float* __restrict__ out) {
    int b  = blockIdx.y;
    int sp = blockIdx.x;     // 0..NSPLIT-1
    int t  = threadIdx.x;    // 0..255
    int l0 = sp * ROWS_PER_SPLIT;

    __shared__ float sa[ROWS_PER_SPLIT];
    __shared__ int s_last;
    if (t < ROWS_PER_SPLIT) sa[t] = attn[b * Lx + l0 + t];
    __syncthreads();

    const float4* base = (const float4*)eo + ((size_t)(b * Lx + l0)) * (Dx / 4) + t;
    float4 acc = make_float4(0.f, 0.f, 0.f, 0.f);
#pragma unroll 2
    for (int i = 0; i < ROWS_PER_SPLIT; i += 4) {
        float4 v0 = __ldcs(base + (size_t)(i + 0) * (Dx / 4));
        float4 v1 = __ldcs(base + (size_t)(i + 1) * (Dx / 4));
        float4 v2 = __ldcs(base + (size_t)(i + 2) * (Dx / 4));
        float4 v3 = __ldcs(base + (size_t)(i + 3) * (Dx / 4));
        float a0 = sa[i], a1 = sa[i + 1], a2 = sa[i + 2], a3 = sa[i + 3];
        acc.x = fmaf(a0, v0.x, acc.x); acc.y = fmaf(a0, v0.y, acc.y);
        acc.z = fmaf(a0, v0.z, acc.z); acc.w = fmaf(a0, v0.w, acc.w);
        acc.x = fmaf(a1, v1.x, acc.x); acc.y = fmaf(a1, v1.y, acc.y);
        acc.z = fmaf(a1, v1.z, acc.z); acc.w = fmaf(a1, v1.w, acc.w);
        acc.x = fmaf(a2, v2.x, acc.x); acc.y = fmaf(a2, v2.y, acc.y);
        acc.z = fmaf(a2, v2.z, acc.z); acc.w = fmaf(a2, v2.w, acc.w);
        acc.x = fmaf(a3, v3.x, acc.x); acc.y = fmaf(a3, v3.y, acc.y);
        acc.z = fmaf(a3, v3.z, acc.z); acc.w = fmaf(a3, v3.w, acc.w);
    }
    ((float4*)(g_partial + ((size_t)(b * NSPLIT + sp)) * Dx))[t] = acc;

    __syncthreads();              // ALL warps' partial stores precede signal
    if (t == 0) {
        __threadfence();
        int old = atomicAdd(&g_ctr_c[b], 1);
        s_last = (old == NSPLIT - 1);
        if (s_last) g_ctr_c[b] = 0;   // reset for next graph replay
    }
    __syncthreads();
    if (!s_last) return;
    __threadfence();

    float4 sum = make_float4(0.f, 0.f, 0.f, 0.f);
#pragma unroll
    for (int s = 0; s < NSPLIT; s++) {
        float4 p = ((const float4*)(g_partial + ((size_t)(b * NSPLIT + s)) * Dx))[t];
        sum.x += p.x; sum.y += p.y; sum.z += p.z; sum.w += p.w;
    }
    ((float4*)(out + CTX_OFF + (size_t)b * Dx))[t] = sum;
}

// ============================================================
extern "C" void kernel_launch(void* const* d_in, const int* in_sizes, int n_in,
                              void* d_out, int out_size) {
    const float* dec_hidden  = (const float*)d_in[0];
    const float* enc_output  = (const float*)d_in[1];
    const float* enc_feature = (const float*)d_in[2];
    const float* enc_mask    = (const float*)d_in[3];
    // d_in[4] = sec_attn : dead code in reference
    const float* coverage    = (const float*)d_in[5];
    const float* W_feat      = (const float*)d_in[6];
    const float* b_feat      = (const float*)d_in[7];
    const float* w_score     = (const float*)d_in[8];
    const float* w_cov       = (const float*)d_in[9];
    float* out = (float*)d_out;

    k_decfeat<<<Dx, 256>>>(dec_hidden, W_feat, b_feat);
    k_score  <<<dim3(NSBLK, Bx), 256>>>(enc_feature, coverage, w_score, w_cov,
                                        enc_mask, out);
    k_context<<<dim3(NSPLIT, Bx), 256>>>(enc_output, out + ATTN_OFF, out);
}

// round 6
// speedup vs baseline: 1.1016x; 1.1016x over previous
#include <cuda_runtime.h>
#include <cstddef>

#define Bx 16
#define Lx 4096
#define Dx 1024
#define NSPLIT 64
#define ROWS_PER_SPLIT (Lx / NSPLIT)   // 64

// ---- scratch (__device__ globals; no allocation allowed) ----
__device__ float g_df[Bx * Dx];               // dec_feature
__device__ float g_score[Bx * Lx];            // pre-softmax scores
__device__ float g_partial[Bx * NSPLIT * Dx]; // context partials

// d_out layout (float32): attn, context, new_coverage
#define ATTN_OFF 0
#define CTX_OFF  (Bx * Lx)
#define COV_OFF  (Bx * Lx + Bx * Dx)

__device__ __forceinline__ float tanh_approx(float x) {
    float y;
    asm("tanh.approx.f32 %0, %1;" : "=f"(y) : "f"(x));
    return y;
}

// ============================================================
// Kernel 1: dec_feature. grid (Dx, 2): block = one d, 8 batches.
// Per thread: 1 W float4 + 8 dh float4, 32 FMA, merging butterfly.
// ============================================================
__global__ void k_decfeat(const float* __restrict__ dh,
                          const float* __restrict__ W,
                          const float* __restrict__ bias) {
    int d  = blockIdx.x;
    int bh = blockIdx.y;               // batch half: b in [8*bh, 8*bh+8)
    int t = threadIdx.x, warp = t >> 5, lane = t & 31;

    float4 w4 = ((const float4*)(W + (size_t)d * Dx))[t];

    float acc[8];
#pragma unroll
    for (int i = 0; i < 8; i++) {
        float4 h4 = ((const float4*)(dh + (size_t)(bh * 8 + i) * Dx))[t];
        acc[i] = w4.x * h4.x + w4.y * h4.y + w4.z * h4.z + w4.w * h4.w;
    }

    // merging butterfly: 8 values -> 1 per lane-group
    bool hi = (lane & 16) != 0;        // xor16: keep 4, b_loc = i + 4*hi
#pragma unroll
    for (int i = 0; i < 4; i++) {
        float send = hi ? acc[i] : acc[i + 4];
        float r = __shfl_xor_sync(0xffffffffu, send, 16);
        acc[i] = (hi ? acc[i + 4] : acc[i]) + r;
    }
    bool h2 = (lane & 8) != 0;         // xor8: keep 2, b_loc = i + 2*h2 + 4*hi
#pragma unroll
    for (int i = 0; i < 2; i++) {
        float send = h2 ? acc[i] : acc[i + 2];
        float r = __shfl_xor_sync(0xffffffffu, send, 8);
        acc[i] = (h2 ? acc[i + 2] : acc[i]) + r;
    }
    bool h3 = (lane & 4) != 0;         // xor4: keep 1, b_loc = (lane>>2)&7
    {
        float send = h3 ? acc[0] : acc[1];
        float r = __shfl_xor_sync(0xffffffffu, send, 4);
        acc[0] = (h3 ? acc[1] : acc[0]) + r;
    }
    acc[0] += __shfl_xor_sync(0xffffffffu, acc[0], 2);   // finish 4-lane group
    acc[0] += __shfl_xor_sync(0xffffffffu, acc[0], 1);

    __shared__ float s[8][8];
    if ((lane & 3) == 0) s[warp][(lane >> 2) & 7] = acc[0];
    __syncthreads();
    if (t < 8) {
        float v = 0.f;
#pragma unroll
        for (int w = 0; w < 8; w++) v += s[w][t];
        g_df[(bh * 8 + t) * Dx + d] = v + bias[d];
    }
}

// ============================================================
// Kernel 2: score[b,l] = sum_d tanh(ef + df + cov*w_cov) * w_score
// (R2 version: warp-per-row, smem weights). HBM bound.
// ============================================================
__global__ void k_score(const float* __restrict__ ef,
                        const float* __restrict__ cov,
                        const float* __restrict__ wscore,
                        const float* __restrict__ wcov) {
    int b  = blockIdx.y;
    int l0 = blockIdx.x * 8;
    int t  = threadIdx.x;

    __shared__ float4 s_df[Dx / 4], s_ws[Dx / 4], s_wc[Dx / 4];
    s_df[t] = ((const float4*)(g_df + (size_t)b * Dx))[t];
    s_ws[t] = ((const float4*)wscore)[t];
    s_wc[t] = ((const float4*)wcov)[t];
    __syncthreads();

    int warp = t >> 5, lane = t & 31;
    int l = l0 + warp;
    float c = cov[b * Lx + l];
    const float4* row = (const float4*)(ef + ((size_t)b * Lx + l) * Dx);

    float sum = 0.f;
#pragma unroll
    for (int j = 0; j < 8; j++) {
        int idx = lane + j * 32;
        float4 e  = row[idx];
        float4 dv = s_df[idx];
        float4 wc = s_wc[idx];
        float4 ws = s_ws[idx];
        sum += tanh_approx(fmaf(c, wc.x, e.x + dv.x)) * ws.x
             + tanh_approx(fmaf(c, wc.y, e.y + dv.y)) * ws.y
             + tanh_approx(fmaf(c, wc.z, e.z + dv.z)) * ws.z
             + tanh_approx(fmaf(c, wc.w, e.w + dv.w)) * ws.w;
    }
#pragma unroll
    for (int off = 16; off; off >>= 1)
        sum += __shfl_down_sync(0xffffffffu, sum, off);
    if (lane == 0) g_score[b * Lx + l] = sum;
}

// ============================================================
// Kernel 3: masked softmax + renormalize -> attn & new_coverage.
// softmax -> *mask -> /sum collapses to e*m / sum(e*m).
// ============================================================
__global__ void k_softmax(const float* __restrict__ mask,
                          const float* __restrict__ cov,
                          float* __restrict__ out) {
    int b = blockIdx.x;
    int t = threadIdx.x;
    __shared__ float red[32];
    __shared__ float bcast;

    float s[4], em[4];
#pragma unroll
    for (int i = 0; i < 4; i++) s[i] = g_score[b * Lx + t + i * 1024];

    float mx = fmaxf(fmaxf(s[0], s[1]), fmaxf(s[2], s[3]));
#pragma unroll
    for (int off = 16; off; off >>= 1)
        mx = fmaxf(mx, __shfl_xor_sync(0xffffffffu, mx, off));
    if ((t & 31) == 0) red[t >> 5] = mx;
    __syncthreads();
    if (t < 32) {
        float v = red[t];
#pragma unroll
        for (int off = 16; off; off >>= 1)
            v = fmaxf(v, __shfl_xor_sync(0xffffffffu, v, off));
        if (t == 0) bcast = v;
    }
    __syncthreads();
    mx = bcast;

    float lsum = 0.f;
#pragma unroll
    for (int i = 0; i < 4; i++) {
        em[i] = expf(s[i] - mx) * mask[b * Lx + t + i * 1024];
        lsum += em[i];
    }
#pragma unroll
    for (int off = 16; off; off >>= 1)
        lsum += __shfl_xor_sync(0xffffffffu, lsum, off);
    __syncthreads();
    if ((t & 31) == 0) red[t >> 5] = lsum;
    __syncthreads();
    if (t < 32) {
        float v = red[t];
#pragma unroll
        for (int off = 16; off; off >>= 1)
            v += __shfl_xor_sync(0xffffffffu, v, off);
        if (t == 0) bcast = v;
    }
    __syncthreads();
    float inv = 1.f / bcast;

#pragma unroll
    for (int i = 0; i < 4; i++) {
        int idx = b * Lx + t + i * 1024;
        float a = em[i] * inv;
        out[ATTN_OFF + idx] = a;
        out[COV_OFF  + idx] = a + cov[idx];
    }
}

// ============================================================
// Kernel 4: context partials. grid = (NSPLIT, Bx), 256 threads.
// ============================================================
__global__ void k_context(const float* __restrict__ eo,
                          const float* __restrict__ attn) {
    int b  = blockIdx.y;
    int sp = blockIdx.x;     // 0..NSPLIT-1
    int t  = threadIdx.x;    // 0..255
    int l0 = sp * ROWS_PER_SPLIT;

    __shared__ float sa[ROWS_PER_SPLIT];
    if (t < ROWS_PER_SPLIT) sa[t] = attn[b * Lx + l0 + t];
    __syncthreads();

    const float4* base = (const float4*)eo + ((size_t)b * Lx + l0) * (Dx / 4) + t;
    float4 acc = make_float4(0.f, 0.f, 0.f, 0.f);
#pragma unroll 8
    for (int i = 0; i < ROWS_PER_SPLIT; i++) {
        float a = sa[i];
        float4 v = base[(size_t)i * (Dx / 4)];
        acc.x = fmaf(a, v.x, acc.x);
        acc.y = fmaf(a, v.y, acc.y);
        acc.z = fmaf(a, v.z, acc.z);
        acc.w = fmaf(a, v.w, acc.w);
    }
    ((float4*)(g_partial + ((size_t)(b * NSPLIT + sp)) * Dx))[t] = acc;
}

// ============================================================
// Kernel 5: deterministic partial reduce -> context. 16384 outputs.
// ============================================================
__global__ void k_reduce(float* __restrict__ out) {
    int idx = blockIdx.x * 256 + threadIdx.x;   // 0..16383
    int b = idx >> 10, d = idx & 1023;
    float v = 0.f;
#pragma unroll
    for (int s = 0; s < NSPLIT; s++)
        v += g_partial[((size_t)(b * NSPLIT + s) << 10) + d];
    out[CTX_OFF + idx] = v;
}

// ============================================================
extern "C" void kernel_launch(void* const* d_in, const int* in_sizes, int n_in,
                              void* d_out, int out_size) {
    const float* dec_hidden  = (const float*)d_in[0];
    const float* enc_output  = (const float*)d_in[1];
    const float* enc_feature = (const float*)d_in[2];
    const float* enc_mask    = (const float*)d_in[3];
    // d_in[4] = sec_attn : dead code in reference
    const float* coverage    = (const float*)d_in[5];
    const float* W_feat      = (const float*)d_in[6];
    const float* b_feat      = (const float*)d_in[7];
    const float* w_score     = (const float*)d_in[8];
    const float* w_cov       = (const float*)d_in[9];
    float* out = (float*)d_out;

    k_decfeat<<<dim3(Dx, 2), 256>>>(dec_hidden, W_feat, b_feat);
    k_score  <<<dim3(Lx / 8, Bx), 256>>>(enc_feature, coverage, w_score, w_cov);
    k_softmax<<<Bx, 1024>>>(enc_mask, coverage, out);
    k_context<<<dim3(NSPLIT, Bx), 256>>>(enc_output, out + ATTN_OFF);
    k_reduce <<<(Bx * Dx) / 256, 256>>>(out);
}